// round 5
// baseline (speedup 1.0000x reference)
#include <cuda_runtime.h>
#include <cuda_bf16.h>
#include <stdint.h>

#define D_DIM     256
#define NROWS     16384
#define KCB       8192
#define M_TILE    128
#define N_CHUNK   128
#define NUM_CHUNKS 64
#define CAP       96
#define THRESH    32.0f
#define NUM_CTAS  128
#define THREADS   256
#define NELEM     4194304
#define ROWPITCH  272              // 256 int8 + 16 pad (conflict-free for ldmatrix)

// ---------------- SMEM layout ----------------
#define OFF_A      0               // 128*272 = 34816
#define OFF_B0     34816
#define OFF_B1     69632
#define OFF_CNS    104448          // float2[2][128]  (cnorm, scale)
#define OFF_RSCALE 106496          // float[128] (2*sz per row)
#define OFF_CNT    107008          // int[128]
#define OFF_BEST   107520          // int[128]
#define OFF_CAND   108032          // u16[128][96] = 24576
#define SMEM_BYTES 132608

__device__ __align__(16) int8_t g_cb_q[KCB * D_DIM];
__device__ __align__(16) float2 g_cns_scl[KCB];    // (cnorm_f, scale)
__device__ double g_cnorm_d[KCB];
__device__ double g_losspart[NUM_CTAS];

__device__ __forceinline__ uint32_t smem_u32(const void* p) {
    uint32_t a;
    asm("{ .reg .u64 t; cvta.to.shared.u64 t, %1; cvt.u32.u64 %0, t; }" : "=r"(a) : "l"(p));
    return a;
}
__device__ __forceinline__ void cp16(uint32_t dst, const void* src) {
    asm volatile("cp.async.cg.shared.global [%0], [%1], 16;" :: "r"(dst), "l"(src) : "memory");
}
#define CP_COMMIT() asm volatile("cp.async.commit_group;" ::: "memory")
#define CP_WAIT0()  asm volatile("cp.async.wait_group 0;" ::: "memory")

#define LDSM4(r0, r1, r2, r3, a) \
    asm volatile("ldmatrix.sync.aligned.m8n8.x4.shared.b16 {%0,%1,%2,%3}, [%4];" \
                 : "=r"(r0), "=r"(r1), "=r"(r2), "=r"(r3) : "r"(a))

#define MMAI(d, a0, a1, a2, a3, b0, b1) \
    asm volatile("mma.sync.aligned.m16n8k32.row.col.s32.s8.s8.s32 " \
                 "{%0,%1,%2,%3}, {%4,%5,%6,%7}, {%8,%9}, {%0,%1,%2,%3};" \
                 : "+r"((d)[0]), "+r"((d)[1]), "+r"((d)[2]), "+r"((d)[3]) \
                 : "r"(a0), "r"(a1), "r"(a2), "r"(a3), "r"(b0), "r"(b1))

__device__ __forceinline__ int8_t q8(float v, float inv) {
    int q = __float2int_rn(v * inv);
    q = max(-127, min(127, q));
    return (int8_t)q;
}

// ============ prep: int8 codebook + per-row scale + norms ============
__global__ void __launch_bounds__(256) vq_prep(const float* __restrict__ cb) {
    int row = blockIdx.x * 8 + (threadIdx.x >> 5);
    int l = threadIdx.x & 31;
    const float4* p = (const float4*)(cb + (size_t)row * D_DIM);
    float4 a = p[l], b = p[l + 32];   // cols l*4..+3 and 128+l*4..+3

    float m = fmaxf(fmaxf(fabsf(a.x), fabsf(a.y)), fmaxf(fabsf(a.z), fabsf(a.w)));
    m = fmaxf(m, fmaxf(fmaxf(fabsf(b.x), fabsf(b.y)), fmaxf(fabsf(b.z), fabsf(b.w))));
    #pragma unroll
    for (int o = 16; o; o >>= 1) m = fmaxf(m, __shfl_xor_sync(0xffffffffu, m, o));
    float sc = m * (1.0f / 127.0f);
    float inv = (m > 0.0f) ? (127.0f / m) : 0.0f;

    char4 qa = { q8(a.x, inv), q8(a.y, inv), q8(a.z, inv), q8(a.w, inv) };
    char4 qb = { q8(b.x, inv), q8(b.y, inv), q8(b.z, inv), q8(b.w, inv) };
    *(char4*)(g_cb_q + (size_t)row * D_DIM + l * 4) = qa;
    *(char4*)(g_cb_q + (size_t)row * D_DIM + 128 + l * 4) = qb;

    double s = (double)a.x * a.x + (double)a.y * a.y + (double)a.z * a.z + (double)a.w * a.w
             + (double)b.x * b.x + (double)b.y * b.y + (double)b.z * b.z + (double)b.w * b.w;
    #pragma unroll
    for (int o = 16; o; o >>= 1) s += __shfl_xor_sync(0xffffffffu, s, o);
    if (l == 0) {
        g_cnorm_d[row] = s;
        g_cns_scl[row] = make_float2((float)s, sc);
    }
}

// ============ main: IMMA GEMM + filter + fp64 rescore + gather ============
__global__ void __launch_bounds__(THREADS, 1)
vq_main(const float* __restrict__ z, const float* __restrict__ cb,
        float* __restrict__ zq_out) {
    extern __shared__ char smem[];
    const uint32_t sbase = smem_u32(smem);
    const int tid = threadIdx.x;
    const int lane = tid & 31;
    const int w = tid >> 5;
    const int R0 = blockIdx.x * M_TILE;

    const int rb = (w >> 1) * 32;      // warp's 32-row block
    const int half = w & 1;            // warp's 64-col half
    const int colbase = half * 64;

    const uint32_t aoff = sbase + OFF_A + (uint32_t)(rb + (lane & 15)) * ROWPITCH
                        + ((lane >> 4) ? 16u : 0u);
    const uint32_t boff = (uint32_t)(colbase + ((lane >> 4) & 1) * 8 + (lane & 7)) * ROWPITCH
                        + ((lane >> 3) & 1) * 16u;

    if (tid < 128) ((int*)(smem + OFF_CNT))[tid] = 0;

    // ---- A tile: quantize z rows to int8, per-row scale ----
    {
        for (int rr = 0; rr < 16; ++rr) {
            int r = w * 16 + rr;
            const float4* zp = (const float4*)(z + (size_t)(R0 + r) * D_DIM);
            float4 a = zp[2 * lane], b = zp[2 * lane + 1];   // cols lane*8..+7
            float m = fmaxf(fmaxf(fabsf(a.x), fabsf(a.y)), fmaxf(fabsf(a.z), fabsf(a.w)));
            m = fmaxf(m, fmaxf(fmaxf(fabsf(b.x), fabsf(b.y)), fmaxf(fabsf(b.z), fabsf(b.w))));
            #pragma unroll
            for (int o = 16; o; o >>= 1) m = fmaxf(m, __shfl_xor_sync(0xffffffffu, m, o));
            float inv = (m > 0.0f) ? (127.0f / m) : 0.0f;
            char qv[8] = { q8(a.x, inv), q8(a.y, inv), q8(a.z, inv), q8(a.w, inv),
                           q8(b.x, inv), q8(b.y, inv), q8(b.z, inv), q8(b.w, inv) };
            *(uint2*)(smem + OFF_A + r * ROWPITCH + lane * 8) = *(uint2*)qv;
            if (lane == 0)
                ((float*)(smem + OFF_RSCALE))[r] = 2.0f * m * (1.0f / 127.0f);
        }
    }
    // ---- chunk 0 via cp.async ----
    {
        uint32_t dstb = sbase + OFF_B0;
        #pragma unroll
        for (int it = 0; it < 8; ++it) {
            int g = tid + it * THREADS;                 // 2048 x 16B
            cp16(dstb + (g >> 4) * ROWPITCH + (g & 15) * 16,
                 g_cb_q + (size_t)g * 16);
        }
        if (tid < 64) cp16(sbase + OFF_CNS + tid * 16, (const char*)g_cns_scl + tid * 16);
        CP_COMMIT();
    }
    CP_WAIT0();
    __syncthreads();

    // preload per-row 2*sz for this thread's 4 row groups
    float two_sz[4];
    #pragma unroll
    for (int j = 0; j < 4; ++j) {
        int row = rb + (j >> 1) * 16 + (j & 1) * 8 + (lane >> 2);
        two_sz[j] = ((const float*)(smem + OFF_RSCALE))[row];
    }

    unsigned short* cand = (unsigned short*)(smem + OFF_CAND);
    int* cnt = (int*)(smem + OFF_CNT);
    float runmin[4] = { __int_as_float(0x7f800000), __int_as_float(0x7f800000),
                        __int_as_float(0x7f800000), __int_as_float(0x7f800000) };

    for (int c = 0; c < NUM_CHUNKS; ++c) {
        const int cur = c & 1;
        if (c + 1 < NUM_CHUNKS) {   // prefetch next chunk
            const int nxt = cur ^ 1;
            const int8_t* src = g_cb_q + (size_t)(c + 1) * N_CHUNK * D_DIM;
            uint32_t dstb = sbase + (nxt ? OFF_B1 : OFF_B0);
            #pragma unroll
            for (int it = 0; it < 8; ++it) {
                int g = tid + it * THREADS;
                cp16(dstb + (g >> 4) * ROWPITCH + (g & 15) * 16, src + (size_t)g * 16);
            }
            if (tid < 64)
                cp16(sbase + OFF_CNS + nxt * 1024 + tid * 16,
                     (const char*)(g_cns_scl + (c + 1) * 128) + tid * 16);
            CP_COMMIT();
        }

        // ---- IMMA GEMM: 32 rows x 64 cols, K=256 int8 ----
        int acc[2][8][4];
        #pragma unroll
        for (int rg = 0; rg < 2; ++rg)
            #pragma unroll
            for (int nt = 0; nt < 8; ++nt)
                #pragma unroll
                for (int d = 0; d < 4; ++d) acc[rg][nt][d] = 0;

        const uint32_t sB = sbase + (cur ? OFF_B1 : OFF_B0) + boff;
        #pragma unroll
        for (int ks = 0; ks < 8; ++ks) {               // 32 int8 K per step
            uint32_t a0, a1, a2, a3, a4, a5, a6, a7;
            LDSM4(a0, a1, a2, a3, aoff + ks * 32);
            LDSM4(a4, a5, a6, a7, aoff + 16 * ROWPITCH + ks * 32);
            #pragma unroll
            for (int p = 0; p < 4; ++p) {
                uint32_t b0, b1, b2, b3;
                LDSM4(b0, b1, b2, b3, sB + p * (16 * ROWPITCH) + ks * 32);
                MMAI(acc[0][2 * p],     a0, a1, a2, a3, b0, b1);
                MMAI(acc[0][2 * p + 1], a0, a1, a2, a3, b2, b3);
                MMAI(acc[1][2 * p],     a4, a5, a6, a7, b0, b1);
                MMAI(acc[1][2 * p + 1], a4, a5, a6, a7, b2, b3);
            }
        }

        // ---- scores + per-row (warp-local) min ----
        const float2* cs = (const float2*)(smem + OFF_CNS) + cur * 128;
        float sc_[2][8][4];
        float m[4] = { __int_as_float(0x7f800000), __int_as_float(0x7f800000),
                       __int_as_float(0x7f800000), __int_as_float(0x7f800000) };
        #pragma unroll
        for (int rg = 0; rg < 2; ++rg)
            #pragma unroll
            for (int nt = 0; nt < 8; ++nt) {
                int c0 = colbase + nt * 8 + (lane & 3) * 2;
                float2 n0 = cs[c0], n1 = cs[c0 + 1];
                float s0 = fmaf(-two_sz[rg * 2],     n0.y * (float)acc[rg][nt][0], n0.x);
                float s1 = fmaf(-two_sz[rg * 2],     n1.y * (float)acc[rg][nt][1], n1.x);
                float s2 = fmaf(-two_sz[rg * 2 + 1], n0.y * (float)acc[rg][nt][2], n0.x);
                float s3 = fmaf(-two_sz[rg * 2 + 1], n1.y * (float)acc[rg][nt][3], n1.x);
                sc_[rg][nt][0] = s0; sc_[rg][nt][1] = s1;
                sc_[rg][nt][2] = s2; sc_[rg][nt][3] = s3;
                m[rg * 2]     = fminf(m[rg * 2],     fminf(s0, s1));
                m[rg * 2 + 1] = fminf(m[rg * 2 + 1], fminf(s2, s3));
            }
        #pragma unroll
        for (int j = 0; j < 4; ++j) {
            m[j] = fminf(m[j], __shfl_xor_sync(0xffffffffu, m[j], 1));
            m[j] = fminf(m[j], __shfl_xor_sync(0xffffffffu, m[j], 2));
            runmin[j] = fminf(runmin[j], m[j]);
        }

        // ---- candidate append ----
        #pragma unroll
        for (int j = 0; j < 4; ++j) {
            int row = rb + (j >> 1) * 16 + (j & 1) * 8 + (lane >> 2);
            float thr = runmin[j] + THRESH;
            int rg = j >> 1, dh = (j & 1) * 2;
            #pragma unroll
            for (int nt = 0; nt < 8; ++nt) {
                int c0 = c * N_CHUNK + colbase + nt * 8 + (lane & 3) * 2;
                if (sc_[rg][nt][dh] < thr) {
                    int ix = atomicAdd(&cnt[row], 1);
                    if (ix < CAP) cand[row * CAP + ix] = (unsigned short)c0;
                }
                if (sc_[rg][nt][dh + 1] < thr) {
                    int ix = atomicAdd(&cnt[row], 1);
                    if (ix < CAP) cand[row * CAP + ix] = (unsigned short)(c0 + 1);
                }
            }
        }
        CP_WAIT0();
        __syncthreads();
    }

    // ---- exact fp64 rescore: warp w -> rows w*16 .. w*16+15 ----
    for (int rr = 0; rr < 16; ++rr) {
        int r = w * 16 + rr;
        int R = R0 + r;
        const float4* zp = (const float4*)(z + (size_t)R * D_DIM);
        float4 za = zp[lane], zb = zp[lane + 32];
        int rcnt = cnt[r];
        double best = 1e300;
        int bestj = 0;
        int total = (rcnt > CAP) ? KCB : rcnt;
        for (int ci = 0; ci < total; ++ci) {
            int j = (rcnt > CAP) ? ci : cand[r * CAP + ci];
            const float4* cp = (const float4*)(cb + (size_t)j * D_DIM);
            float4 ca = cp[lane], cv = cp[lane + 32];
            double d = (double)za.x * ca.x + (double)za.y * ca.y +
                       (double)za.z * ca.z + (double)za.w * ca.w +
                       (double)zb.x * cv.x + (double)zb.y * cv.y +
                       (double)zb.z * cv.z + (double)zb.w * cv.w;
            #pragma unroll
            for (int o = 16; o; o >>= 1) d += __shfl_xor_sync(0xffffffffu, d, o);
            double s = g_cnorm_d[j] - 2.0 * d;
            if (s < best) { best = s; bestj = j; }
        }
        if (lane == 0) ((int*)(smem + OFF_BEST))[r] = bestj;
    }
    __syncthreads();

    // ---- gather z_q + loss partial ----
    double lsum = 0.0;
    {
        const int sub = tid >> 6, l64 = tid & 63;
        for (int it = 0; it < 32; ++it) {
            int r = it * 4 + sub;
            int R = R0 + r;
            int j = ((const int*)(smem + OFF_BEST))[r];
            float4 q  = ((const float4*)(cb + (size_t)j * D_DIM))[l64];
            float4 ze = ((const float4*)(z  + (size_t)R * D_DIM))[l64];
            float* o = zq_out + (size_t)R * D_DIM + l64 * 4;   // base is odd-offset
            o[0] = q.x; o[1] = q.y; o[2] = q.z; o[3] = q.w;
            float dx = q.x - ze.x, dy = q.y - ze.y, dz = q.z - ze.z, dw = q.w - ze.w;
            lsum += (double)dx * dx + (double)dy * dy + (double)dz * dz + (double)dw * dw;
        }
    }
    __syncthreads();
    double* red = (double*)(smem + OFF_CAND);
    red[tid] = lsum;
    __syncthreads();
    #pragma unroll
    for (int s = 128; s > 0; s >>= 1) {
        if (tid < s) red[tid] += red[tid + s];
        __syncthreads();
    }
    if (tid == 0) g_losspart[blockIdx.x] = red[0];
}

// ======================= loss reduction =======================
__global__ void vq_reduce(float* __restrict__ out_loss) {
    __shared__ double red[128];
    int t = threadIdx.x;
    red[t] = g_losspart[t];
    __syncthreads();
    #pragma unroll
    for (int k = 64; k > 0; k >>= 1) {
        if (t < k) red[t] += red[t + k];
        __syncthreads();
    }
    if (t == 0) out_loss[0] = (float)(2.0 * red[0] / (double)NELEM);
}

extern "C" void kernel_launch(void* const* d_in, const int* in_sizes, int n_in,
                              void* d_out, int out_size) {
    const float* z  = (const float*)d_in[0];
    const float* cb = (const float*)d_in[1];
    float* out = (float*)d_out;
    // output layout: [z_e (4194304) | loss (1) | z_q_st (4194304)]
    cudaFuncSetAttribute(vq_main, cudaFuncAttributeMaxDynamicSharedMemorySize, SMEM_BYTES);
    cudaMemcpyAsync(out, z, (size_t)NELEM * sizeof(float), cudaMemcpyDeviceToDevice);
    vq_prep<<<KCB / 8, 256>>>(cb);
    vq_main<<<NUM_CTAS, THREADS, SMEM_BYTES>>>(z, cb, out + NELEM + 1);
    vq_reduce<<<1, 128>>>(out + NELEM);
}

// round 14
// speedup vs baseline: 142.7724x; 142.7724x over previous
#include <cuda_runtime.h>
#include <cuda_bf16.h>
#include <stdint.h>

#define D_DIM     256
#define NROWS     16384
#define KCB       8192
#define M_TILE    128
#define N_CHUNK   128
#define NUM_CHUNKS 64
#define CAP       96
#define THRESH    5.0f
#define NUM_CTAS  128
#define THREADS   256
#define NELEM     4194304
#define ROWPITCH  272              // 256 int8 + 16 pad (conflict-free for ldmatrix)

// ---------------- SMEM layout ----------------
#define OFF_A      0               // 128*272 = 34816
#define OFF_B0     34816
#define OFF_B1     69632
#define OFF_CNS    104448          // float2[2][128]  (cnorm, scale)
#define OFF_RSCALE 106496          // float[128] (2*sz per row)
#define OFF_CNT    107008          // int[128]
#define OFF_BEST   107520          // int[128]
#define OFF_CAND   108032          // u16[128][96] = 24576
#define SMEM_BYTES 132608

__device__ __align__(16) int8_t g_cb_q[KCB * D_DIM];
__device__ __align__(16) float2 g_cns_scl[KCB];    // (cnorm_f, scale)
__device__ double g_cnorm_d[KCB];
__device__ double g_losspart[NUM_CTAS];

__device__ __forceinline__ uint32_t smem_u32(const void* p) {
    uint32_t a;
    asm("{ .reg .u64 t; cvta.to.shared.u64 t, %1; cvt.u32.u64 %0, t; }" : "=r"(a) : "l"(p));
    return a;
}
__device__ __forceinline__ void cp16(uint32_t dst, const void* src) {
    asm volatile("cp.async.cg.shared.global [%0], [%1], 16;" :: "r"(dst), "l"(src) : "memory");
}
#define CP_COMMIT() asm volatile("cp.async.commit_group;" ::: "memory")
#define CP_WAIT0()  asm volatile("cp.async.wait_group 0;" ::: "memory")

#define LDSM4(r0, r1, r2, r3, a) \
    asm volatile("ldmatrix.sync.aligned.m8n8.x4.shared.b16 {%0,%1,%2,%3}, [%4];" \
                 : "=r"(r0), "=r"(r1), "=r"(r2), "=r"(r3) : "r"(a))

#define MMAI(d, a0, a1, a2, a3, b0, b1) \
    asm volatile("mma.sync.aligned.m16n8k32.row.col.s32.s8.s8.s32 " \
                 "{%0,%1,%2,%3}, {%4,%5,%6,%7}, {%8,%9}, {%0,%1,%2,%3};" \
                 : "+r"((d)[0]), "+r"((d)[1]), "+r"((d)[2]), "+r"((d)[3]) \
                 : "r"(a0), "r"(a1), "r"(a2), "r"(a3), "r"(b0), "r"(b1))

__device__ __forceinline__ int8_t q8(float v, float inv) {
    int q = __float2int_rn(v * inv);
    q = max(-127, min(127, q));
    return (int8_t)q;
}

// ============ prep: int8 codebook + per-row scale + norms ============
__global__ void __launch_bounds__(256) vq_prep(const float* __restrict__ cb) {
    int row = blockIdx.x * 8 + (threadIdx.x >> 5);
    int l = threadIdx.x & 31;
    const float4* p = (const float4*)(cb + (size_t)row * D_DIM);
    float4 a = p[l], b = p[l + 32];

    float m = fmaxf(fmaxf(fabsf(a.x), fabsf(a.y)), fmaxf(fabsf(a.z), fabsf(a.w)));
    m = fmaxf(m, fmaxf(fmaxf(fabsf(b.x), fabsf(b.y)), fmaxf(fabsf(b.z), fabsf(b.w))));
    #pragma unroll
    for (int o = 16; o; o >>= 1) m = fmaxf(m, __shfl_xor_sync(0xffffffffu, m, o));
    float sc = m * (1.0f / 127.0f);
    float inv = (m > 0.0f) ? (127.0f / m) : 0.0f;

    char4 qa = { q8(a.x, inv), q8(a.y, inv), q8(a.z, inv), q8(a.w, inv) };
    char4 qb = { q8(b.x, inv), q8(b.y, inv), q8(b.z, inv), q8(b.w, inv) };
    *(char4*)(g_cb_q + (size_t)row * D_DIM + l * 4) = qa;
    *(char4*)(g_cb_q + (size_t)row * D_DIM + 128 + l * 4) = qb;

    double s = (double)a.x * a.x + (double)a.y * a.y + (double)a.z * a.z + (double)a.w * a.w
             + (double)b.x * b.x + (double)b.y * b.y + (double)b.z * b.z + (double)b.w * b.w;
    #pragma unroll
    for (int o = 16; o; o >>= 1) s += __shfl_xor_sync(0xffffffffu, s, o);
    if (l == 0) {
        g_cnorm_d[row] = s;
        g_cns_scl[row] = make_float2((float)s, sc);
    }
}

// ============ main: IMMA GEMM + filter + fp64 rescore + gather ============
__global__ void __launch_bounds__(THREADS, 1)
vq_main(const float* __restrict__ z, const float* __restrict__ cb,
        float* __restrict__ zq_out) {
    extern __shared__ char smem[];
    const uint32_t sbase = smem_u32(smem);
    const int tid = threadIdx.x;
    const int lane = tid & 31;
    const int w = tid >> 5;
    const int R0 = blockIdx.x * M_TILE;

    const int rb = (w >> 1) * 32;      // warp's 32-row block
    const int half = w & 1;            // warp's 64-col half
    const int colbase = half * 64;

    const uint32_t aoff = sbase + OFF_A + (uint32_t)(rb + (lane & 15)) * ROWPITCH
                        + ((lane >> 4) ? 16u : 0u);
    const uint32_t boff = (uint32_t)(colbase + ((lane >> 4) & 1) * 8 + (lane & 7)) * ROWPITCH
                        + ((lane >> 3) & 1) * 16u;

    if (tid < 128) ((int*)(smem + OFF_CNT))[tid] = 0;

    // ---- A tile: quantize z rows to int8, per-row scale ----
    {
        for (int rr = 0; rr < 16; ++rr) {
            int r = w * 16 + rr;
            const float4* zp = (const float4*)(z + (size_t)(R0 + r) * D_DIM);
            float4 a = zp[2 * lane], b = zp[2 * lane + 1];
            float m = fmaxf(fmaxf(fabsf(a.x), fabsf(a.y)), fmaxf(fabsf(a.z), fabsf(a.w)));
            m = fmaxf(m, fmaxf(fmaxf(fabsf(b.x), fabsf(b.y)), fmaxf(fabsf(b.z), fabsf(b.w))));
            #pragma unroll
            for (int o = 16; o; o >>= 1) m = fmaxf(m, __shfl_xor_sync(0xffffffffu, m, o));
            float inv = (m > 0.0f) ? (127.0f / m) : 0.0f;
            char qv[8] = { q8(a.x, inv), q8(a.y, inv), q8(a.z, inv), q8(a.w, inv),
                           q8(b.x, inv), q8(b.y, inv), q8(b.z, inv), q8(b.w, inv) };
            *(uint2*)(smem + OFF_A + r * ROWPITCH + lane * 8) = *(uint2*)qv;
            if (lane == 0)
                ((float*)(smem + OFF_RSCALE))[r] = 2.0f * m * (1.0f / 127.0f);
        }
    }
    // ---- chunk 0 via cp.async ----
    {
        uint32_t dstb = sbase + OFF_B0;
        #pragma unroll
        for (int it = 0; it < 8; ++it) {
            int g = tid + it * THREADS;
            cp16(dstb + (g >> 4) * ROWPITCH + (g & 15) * 16,
                 g_cb_q + (size_t)g * 16);
        }
        if (tid < 64) cp16(sbase + OFF_CNS + tid * 16, (const char*)g_cns_scl + tid * 16);
        CP_COMMIT();
    }
    CP_WAIT0();
    __syncthreads();

    float two_sz[4];
    #pragma unroll
    for (int j = 0; j < 4; ++j) {
        int row = rb + (j >> 1) * 16 + (j & 1) * 8 + (lane >> 2);
        two_sz[j] = ((const float*)(smem + OFF_RSCALE))[row];
    }

    unsigned short* cand = (unsigned short*)(smem + OFF_CAND);
    int* cnt = (int*)(smem + OFF_CNT);
    float runmin[4] = { __int_as_float(0x7f800000), __int_as_float(0x7f800000),
                        __int_as_float(0x7f800000), __int_as_float(0x7f800000) };

    for (int c = 0; c < NUM_CHUNKS; ++c) {
        const int cur = c & 1;
        if (c + 1 < NUM_CHUNKS) {   // prefetch next chunk
            const int nxt = cur ^ 1;
            const int8_t* src = g_cb_q + (size_t)(c + 1) * N_CHUNK * D_DIM;
            uint32_t dstb = sbase + (nxt ? OFF_B1 : OFF_B0);
            #pragma unroll
            for (int it = 0; it < 8; ++it) {
                int g = tid + it * THREADS;
                cp16(dstb + (g >> 4) * ROWPITCH + (g & 15) * 16, src + (size_t)g * 16);
            }
            if (tid < 64)
                cp16(sbase + OFF_CNS + nxt * 1024 + tid * 16,
                     (const char*)(g_cns_scl + (c + 1) * 128) + tid * 16);
            CP_COMMIT();
        }

        // ---- IMMA GEMM: 32 rows x 64 cols, K=256 int8 ----
        int acc[2][8][4];
        #pragma unroll
        for (int rg = 0; rg < 2; ++rg)
            #pragma unroll
            for (int nt = 0; nt < 8; ++nt)
                #pragma unroll
                for (int d = 0; d < 4; ++d) acc[rg][nt][d] = 0;

        const uint32_t sB = sbase + (cur ? OFF_B1 : OFF_B0) + boff;
        #pragma unroll
        for (int ks = 0; ks < 8; ++ks) {               // 32 int8 K per step
            uint32_t a0, a1, a2, a3, a4, a5, a6, a7;
            LDSM4(a0, a1, a2, a3, aoff + ks * 32);
            LDSM4(a4, a5, a6, a7, aoff + 16 * ROWPITCH + ks * 32);
            #pragma unroll
            for (int p = 0; p < 4; ++p) {
                uint32_t b0, b1, b2, b3;
                LDSM4(b0, b1, b2, b3, sB + p * (16 * ROWPITCH) + ks * 32);
                MMAI(acc[0][2 * p],     a0, a1, a2, a3, b0, b1);
                MMAI(acc[0][2 * p + 1], a0, a1, a2, a3, b2, b3);
                MMAI(acc[1][2 * p],     a4, a5, a6, a7, b0, b1);
                MMAI(acc[1][2 * p + 1], a4, a5, a6, a7, b2, b3);
            }
        }

        // ---- scores + per-row (warp-local) min ----
        const float2* cs = (const float2*)(smem + OFF_CNS) + cur * 128;
        float sc_[2][8][4];
        float m[4] = { __int_as_float(0x7f800000), __int_as_float(0x7f800000),
                       __int_as_float(0x7f800000), __int_as_float(0x7f800000) };
        #pragma unroll
        for (int rg = 0; rg < 2; ++rg)
            #pragma unroll
            for (int nt = 0; nt < 8; ++nt) {
                int c0 = colbase + nt * 8 + (lane & 3) * 2;
                float2 n0 = cs[c0], n1 = cs[c0 + 1];
                float s0 = fmaf(-two_sz[rg * 2],     n0.y * (float)acc[rg][nt][0], n0.x);
                float s1 = fmaf(-two_sz[rg * 2],     n1.y * (float)acc[rg][nt][1], n1.x);
                float s2 = fmaf(-two_sz[rg * 2 + 1], n0.y * (float)acc[rg][nt][2], n0.x);
                float s3 = fmaf(-two_sz[rg * 2 + 1], n1.y * (float)acc[rg][nt][3], n1.x);
                sc_[rg][nt][0] = s0; sc_[rg][nt][1] = s1;
                sc_[rg][nt][2] = s2; sc_[rg][nt][3] = s3;
                m[rg * 2]     = fminf(m[rg * 2],     fminf(s0, s1));
                m[rg * 2 + 1] = fminf(m[rg * 2 + 1], fminf(s2, s3));
            }
        #pragma unroll
        for (int j = 0; j < 4; ++j) {
            m[j] = fminf(m[j], __shfl_xor_sync(0xffffffffu, m[j], 1));
            m[j] = fminf(m[j], __shfl_xor_sync(0xffffffffu, m[j], 2));
            runmin[j] = fminf(runmin[j], m[j]);
        }

        // ---- candidate append (warp-uniform gate per row-group) ----
        #pragma unroll
        for (int j = 0; j < 4; ++j) {
            if (!__any_sync(0xffffffffu, m[j] < runmin[j] + THRESH)) continue;
            int row = rb + (j >> 1) * 16 + (j & 1) * 8 + (lane >> 2);
            float thr = runmin[j] + THRESH;
            int rg = j >> 1, dh = (j & 1) * 2;
            #pragma unroll
            for (int nt = 0; nt < 8; ++nt) {
                int c0 = c * N_CHUNK + colbase + nt * 8 + (lane & 3) * 2;
                if (sc_[rg][nt][dh] < thr) {
                    int ix = atomicAdd(&cnt[row], 1);
                    if (ix < CAP) cand[row * CAP + ix] = (unsigned short)c0;
                }
                if (sc_[rg][nt][dh + 1] < thr) {
                    int ix = atomicAdd(&cnt[row], 1);
                    if (ix < CAP) cand[row * CAP + ix] = (unsigned short)(c0 + 1);
                }
            }
        }
        CP_WAIT0();
        __syncthreads();
    }

    // ---- exact fp64 rescore: warp w -> rows w*16 .. w*16+15 ----
    for (int rr = 0; rr < 16; ++rr) {
        int r = w * 16 + rr;
        int R = R0 + r;
        const float4* zp = (const float4*)(z + (size_t)R * D_DIM);
        float4 za = zp[lane], zb = zp[lane + 32];
        int rcnt = cnt[r];
        double best = 1e300;
        int bestj = 0;
        int total = (rcnt > CAP) ? KCB : rcnt;
        for (int ci = 0; ci < total; ++ci) {
            int j = (rcnt > CAP) ? ci : cand[r * CAP + ci];
            const float4* cp = (const float4*)(cb + (size_t)j * D_DIM);
            float4 ca = cp[lane], cv = cp[lane + 32];
            double d = (double)za.x * ca.x + (double)za.y * ca.y +
                       (double)za.z * ca.z + (double)za.w * ca.w +
                       (double)zb.x * cv.x + (double)zb.y * cv.y +
                       (double)zb.z * cv.z + (double)zb.w * cv.w;
            #pragma unroll
            for (int o = 16; o; o >>= 1) d += __shfl_xor_sync(0xffffffffu, d, o);
            double s = g_cnorm_d[j] - 2.0 * d;
            if (s < best) { best = s; bestj = j; }
        }
        if (lane == 0) ((int*)(smem + OFF_BEST))[r] = bestj;
    }
    __syncthreads();

    // ---- gather z_q + loss partial ----
    double lsum = 0.0;
    {
        const int sub = tid >> 6, l64 = tid & 63;
        for (int it = 0; it < 32; ++it) {
            int r = it * 4 + sub;
            int R = R0 + r;
            int j = ((const int*)(smem + OFF_BEST))[r];
            float4 q  = ((const float4*)(cb + (size_t)j * D_DIM))[l64];
            float4 ze = ((const float4*)(z  + (size_t)R * D_DIM))[l64];
            float* o = zq_out + (size_t)R * D_DIM + l64 * 4;   // base is odd-offset
            o[0] = q.x; o[1] = q.y; o[2] = q.z; o[3] = q.w;
            float dx = q.x - ze.x, dy = q.y - ze.y, dz = q.z - ze.z, dw = q.w - ze.w;
            lsum += (double)dx * dx + (double)dy * dy + (double)dz * dz + (double)dw * dw;
        }
    }
    __syncthreads();
    double* red = (double*)(smem + OFF_CAND);
    red[tid] = lsum;
    __syncthreads();
    #pragma unroll
    for (int s = 128; s > 0; s >>= 1) {
        if (tid < s) red[tid] += red[tid + s];
        __syncthreads();
    }
    if (tid == 0) g_losspart[blockIdx.x] = red[0];
}

// ======================= loss reduction =======================
__global__ void vq_reduce(float* __restrict__ out_loss) {
    __shared__ double red[128];
    int t = threadIdx.x;
    red[t] = g_losspart[t];
    __syncthreads();
    #pragma unroll
    for (int k = 64; k > 0; k >>= 1) {
        if (t < k) red[t] += red[t + k];
        __syncthreads();
    }
    if (t == 0) out_loss[0] = (float)(2.0 * red[0] / (double)NELEM);
}

extern "C" void kernel_launch(void* const* d_in, const int* in_sizes, int n_in,
                              void* d_out, int out_size) {
    const float* z  = (const float*)d_in[0];
    const float* cb = (const float*)d_in[1];
    float* out = (float*)d_out;
    // output layout: [z_e (4194304) | loss (1) | z_q_st (4194304)]
    cudaFuncSetAttribute(vq_main, cudaFuncAttributeMaxDynamicSharedMemorySize, SMEM_BYTES);
    cudaMemcpyAsync(out, z, (size_t)NELEM * sizeof(float), cudaMemcpyDeviceToDevice);
    vq_prep<<<KCB / 8, 256>>>(cb);
    vq_main<<<NUM_CTAS, THREADS, SMEM_BYTES>>>(z, cb, out + NELEM + 1);
    vq_reduce<<<1, 128>>>(out + NELEM);
}